// round 4
// baseline (speedup 1.0000x reference)
#include <cuda_runtime.h>

#define DD 48
#define HH 256
#define WW 256
#define HM 128
#define WM 128
#define PHN 4

// ---------------------------------------------------------------------------
// Trilinear grid-sample of the 2-channel image (zeros padding, align_corners).
// Image viewed as float4[] (two adjacent pixels per element). The two x-corners
// are adjacent, so one aligned float4 covers both when xi is even; a predicated
// second load handles the straddling (odd) case.
// ---------------------------------------------------------------------------
__device__ __forceinline__ float2 sample_img(const float4* __restrict__ img4,
                                             float cz, float cy, float cx)
{
    float zf = floorf(cz), yf = floorf(cy), xf = floorf(cx);
    int zi = (int)zf, yi = (int)yf, xi = (int)xf;
    float wz = cz - zf, wy = cy - yf, wx = cx - xf;

    bool v0 = ((unsigned)xi       < (unsigned)WW);
    bool v1 = ((unsigned)(xi + 1) < (unsigned)WW);
    int  xc0 = min(max(xi,     0), WW - 1);
    int  xc1 = min(max(xi + 1, 0), WW - 1);
    float wx0 = v0 ? (1.0f - wx) : 0.0f;
    float wx1 = v1 ? wx          : 0.0f;
    int  a0 = xc0 >> 1;
    int  a1 = xc1 >> 1;
    bool odd0 = (xc0 & 1);
    bool odd1 = (xc1 & 1);
    bool need2 = (a1 != a0);

    float acc0 = 0.0f, acc1 = 0.0f;
    #pragma unroll
    for (int dz = 0; dz < 2; ++dz) {
        int zz = zi + dz;
        float wzv = dz ? wz : (1.0f - wz);
        int  zc = min(max(zz, 0), DD - 1);
        bool zok = ((unsigned)zz < (unsigned)DD);
        #pragma unroll
        for (int dy = 0; dy < 2; ++dy) {
            int yy = yi + dy;
            float wyv = dy ? wy : (1.0f - wy);
            int  yc = min(max(yy, 0), HH - 1);
            bool yok = ((unsigned)yy < (unsigned)HH);
            float wb = (zok && yok) ? (wzv * wyv) : 0.0f;

            int rb2 = ((zc * HH + yc) * WW) >> 1;   // float4 index of row start
            float4 f0 = __ldg(img4 + rb2 + a0);
            float4 f1 = f0;
            if (need2) f1 = __ldg(img4 + rb2 + a1);

            float p0x = odd0 ? f0.z : f0.x;
            float p0y = odd0 ? f0.w : f0.y;
            float p1x = odd1 ? f1.z : f1.x;
            float p1y = odd1 ? f1.w : f1.y;

            float w0 = wb * wx0;
            float w1 = wb * wx1;
            acc0 += w0 * p0x + w1 * p1x;
            acc1 += w0 * p0y + w1 * p1y;
        }
    }
    return make_float2(acc0, acc1);
}

// ---------------------------------------------------------------------------
// One kernel, grid (HH, DD, 5):
//   blockIdx.z < 4 : fused mvf-upsample + warp for phase p, one output row
//   blockIdx.z ==4 : channel-0 passthrough copy of the same row
// Block = 128 threads; warp path handles 2 pixels/thread (x = 2t, 2t+1).
// ---------------------------------------------------------------------------
__global__ __launch_bounds__(128) void mvf_fused_kernel(
    const float* __restrict__ image,   // [DD][HH][WW][2]
    const float* __restrict__ mvf,     // [PHN][3][DD][HM][WM]
    float* __restrict__ out)           // [5][DD][HH][WW][2]
{
    const int t = threadIdx.x;      // 0..127
    const int y = blockIdx.x;       // 0..255
    const int z = blockIdx.y;       // 0..47
    const int p = blockIdx.z;       // 0..4

    const float4* img4 = (const float4*)image;

    if (p == PHN) {
        // channel-0 copy: one row = 128 float4
        int base4 = (z * HH + y) * (WW * 2 / 4);
        ((float4*)out)[base4 + t] = __ldg(img4 + base4 + t);
        return;
    }

    // ---- stage the two needed mvf rows (y0,y1) x 3 comps into smem ----
    __shared__ float s[3 * 2 * HM];   // [(c*2+r)*128 + xm]

    float fy = fminf(fmaxf(y * 0.5f - 0.25f, 0.0f), (float)(HM - 1));
    int   y0 = (int)fy;
    float wy = fy - (float)y0;
    int   y1 = min(y0 + 1, HM - 1);

    const int mbase = ((p * 3) * DD + z) * (HM * WM);
    const int cstr  = DD * HM * WM;

    #pragma unroll
    for (int k = 0; k < 6; ++k) {
        int c = k >> 1;
        int yr = (k & 1) ? y1 : y0;
        s[k * HM + t] = __ldg(mvf + mbase + c * cstr + yr * WM + t);
    }
    __syncthreads();

    // ---- x interpolation: pixel A (x=2t) taps {cm,t}; pixel B (x=2t+1) {t,cp}
    float fxA = fmaxf((float)t - 0.25f, 0.0f);
    int   cm  = (int)fxA;                 // max(t-1,0)
    float wxA = fxA - (float)cm;          // 0.75 (t>=1) else 0
    float fxB = fminf((float)t + 0.25f, (float)(WM - 1));
    float wxB = fxB - (float)t;           // 0.25 (t<=126) else 0
    int   cp  = min(t + 1, WM - 1);

    float mA[3], mB[3];
    #pragma unroll
    for (int c = 0; c < 3; ++c) {
        const float* s0 = s + (2 * c) * HM;
        const float* s1 = s + (2 * c + 1) * HM;
        float vm0 = s0[cm], v00 = s0[t], vp0 = s0[cp];
        float vm1 = s1[cm], v01 = s1[t], vp1 = s1[cp];
        float a0 = vm0 + wxA * (v00 - vm0);
        float a1 = vm1 + wxA * (v01 - vm1);
        float b0 = v00 + wxB * (vp0 - v00);
        float b1 = v01 + wxB * (vp1 - v01);
        mA[c] = a0 + wy * (a1 - a0);
        mB[c] = b0 + wy * (b1 - b0);
    }

    float2 rA = sample_img(img4, (float)z + mA[0],
                                 (float)y + 2.0f * mA[1],
                                 (float)(2 * t) + 2.0f * mA[2]);
    float2 rB = sample_img(img4, (float)z + mB[0],
                                 (float)y + 2.0f * mB[1],
                                 (float)(2 * t + 1) + 2.0f * mB[2]);

    float4* o = (float4*)(out + ((((1 + p) * DD + z) * HH + y) * WW) * 2) + t;
    *o = make_float4(rA.x, rA.y, rB.x, rB.y);
}

extern "C" void kernel_launch(void* const* d_in, const int* in_sizes, int n_in,
                              void* d_out, int out_size)
{
    const float* image = (const float*)d_in[0];   // 6291456 floats
    const float* mvf   = (const float*)d_in[1];   // 9437184 floats
    float* out = (float*)d_out;                   // 31457280 floats

    dim3 grid(HH, DD, PHN + 1);
    mvf_fused_kernel<<<grid, 128>>>(image, mvf, out);
}

// round 6
// speedup vs baseline: 1.8288x; 1.8288x over previous
#include <cuda_runtime.h>
#include <cuda_fp16.h>

#define DD 48
#define HH 256
#define WW 256
#define HM 128
#define WM 128
#define PHN 4

// fp16-packed image: one half2 (ch0, ch1) per pixel. 48*256*256*4B = 12.6 MB.
__device__ __half2 g_img_h2[DD * HH * WW];

// ---------------------------------------------------------------------------
// Pre-pass: channel-0 copy + fp16 pack, one image read.
// Each thread handles 2 pixels (one float4).
// ---------------------------------------------------------------------------
__global__ __launch_bounds__(256) void convert_kernel(
    const float4* __restrict__ img, float4* __restrict__ out, int n4)
{
    int i = blockIdx.x * blockDim.x + threadIdx.x;
    if (i >= n4) return;
    float4 v = __ldg(img + i);          // pixels 2i, 2i+1
    out[i] = v;                         // channel-0 passthrough
    __half2 a = __floats2half2_rn(v.x, v.y);
    __half2 b = __floats2half2_rn(v.z, v.w);
    g_img_h2[2 * i]     = a;
    g_img_h2[2 * i + 1] = b;
}

// ---------------------------------------------------------------------------
// Fused mvf-upsample + warp. One thread per output voxel (p,z,y,x);
// block = full W row (256 threads) -> warp spans 32 consecutive x.
// Image gather: 8 x LDG.32 from the packed half2 image.
// ---------------------------------------------------------------------------
__global__ __launch_bounds__(256) void mvf_warp_kernel(
    const float* __restrict__ mvf,     // [PHN][3][DD][HM][WM]
    float* __restrict__ out)           // [5][DD][HH][WW][2]
{
    const int x = threadIdx.x;      // 0..255
    const int y = blockIdx.x;       // 0..255
    const int z = blockIdx.y;       // 0..47
    const int p = blockIdx.z;       // 0..3

    // ---- MVF upsample source coords (linear 128->256, clamp) ----
    float fy = fminf(fmaxf(y * 0.5f - 0.25f, 0.0f), (float)(HM - 1));
    float fx = fminf(fmaxf(x * 0.5f - 0.25f, 0.0f), (float)(WM - 1));
    int   y0 = (int)fy;
    int   x0 = (int)fx;
    float wy = fy - (float)y0;
    float wx = fx - (float)x0;
    int   y1 = min(y0 + 1, HM - 1);
    int   x1 = min(x0 + 1, WM - 1);

    const int mbase = ((p * 3) * DD + z) * (HM * WM);
    const int cstr  = DD * HM * WM;

    float m[3];
    #pragma unroll
    for (int c = 0; c < 3; ++c) {
        const float* mp = mvf + mbase + c * cstr;
        float v00 = __ldg(mp + y0 * WM + x0);
        float v01 = __ldg(mp + y0 * WM + x1);
        float v10 = __ldg(mp + y1 * WM + x0);
        float v11 = __ldg(mp + y1 * WM + x1);
        float r0 = v00 + wx * (v01 - v00);
        float r1 = v10 + wx * (v11 - v10);
        m[c] = r0 + wy * (r1 - r0);
    }

    // ---- absolute sample coordinates, flow scaled by (1,2,2) ----
    float cz = (float)z + m[0];
    float cy = (float)y + 2.0f * m[1];
    float cx = (float)x + 2.0f * m[2];

    float zf = floorf(cz), yf = floorf(cy), xf = floorf(cx);
    int   zi = (int)zf,    yi = (int)yf,    xi = (int)xf;
    float wz  = cz - zf;
    float wyy = cy - yf;
    float wxx = cx - xf;

    float acc0 = 0.0f, acc1 = 0.0f;
    #pragma unroll
    for (int dz = 0; dz < 2; ++dz) {
        int zz = zi + dz;
        float wzv = dz ? wz : (1.0f - wz);
        int  zc = min(max(zz, 0), DD - 1);
        bool zok = ((unsigned)zz < (unsigned)DD);
        #pragma unroll
        for (int dy = 0; dy < 2; ++dy) {
            int yy = yi + dy;
            float wyv = dy ? wyy : (1.0f - wyy);
            int  yc = min(max(yy, 0), HH - 1);
            bool yok = ((unsigned)yy < (unsigned)HH);
            int rowbase = (zc * HH + yc) * WW;
            float wb = (zok && yok) ? (wzv * wyv) : 0.0f;
            #pragma unroll
            for (int dx = 0; dx < 2; ++dx) {
                int xx = xi + dx;
                float wxv = dx ? wxx : (1.0f - wxx);
                int  xc = min(max(xx, 0), WW - 1);
                bool ok = ((unsigned)xx < (unsigned)WW);
                float w = ok ? (wb * wxv) : 0.0f;
                __half2 h = g_img_h2[rowbase + xc];
                float2 v = __half22float2(h);
                acc0 += w * v.x;
                acc1 += w * v.y;
            }
        }
    }

    float2* o = (float2*)out + (((1 + p) * DD + z) * HH + y) * WW + x;
    *o = make_float2(acc0, acc1);
}

extern "C" void kernel_launch(void* const* d_in, const int* in_sizes, int n_in,
                              void* d_out, int out_size)
{
    const float* image = (const float*)d_in[0];   // 6291456 floats
    const float* mvf   = (const float*)d_in[1];   // 9437184 floats
    float* out = (float*)d_out;                   // 31457280 floats

    // pre-pass: channel-0 copy + fp16 pack
    const int n4 = (DD * HH * WW * 2) / 4;        // 1572864 float4 (2 px each)
    convert_kernel<<<(n4 + 255) / 256, 256>>>((const float4*)image, (float4*)out, n4);

    // channels 1..4: fused upsample + warp
    dim3 grid(HH, DD, PHN);
    mvf_warp_kernel<<<grid, 256>>>(mvf, out);
}